// round 1
// baseline (speedup 1.0000x reference)
#include <cuda_runtime.h>
#include <cuda_bf16.h>

#define START_ID 62
#define PAD_ID   63
#define BATCH    512
#define SEQ      512
#define LBL      64

__global__ __launch_bounds__(64) void crf_loss_kernel(
    const float* __restrict__ ts,        // [B, S, L]
    const float* __restrict__ Tm,        // [L, L]
    const void*  __restrict__ labels_raw,  // [B, S] int32 or int64
    const void*  __restrict__ lengths_raw, // [B]    int32 or int64
    float* __restrict__ out)
{
    const int b    = blockIdx.x;
    const int j    = threadIdx.x;   // label index 0..63
    const int lane = j & 31;
    const int w    = j >> 5;

    __shared__ float sp[2][LBL];    // exp(alpha - m) double-buffered
    __shared__ float wred[2][2];    // per-warp max, double-buffered
    __shared__ float sred[2];       // generic 2-way reduce scratch

    // ---- dtype detection: int64 data viewed as int32 has word[1]==0
    // (lengths[0] >= 1 and < 2^31, so its high word is 0 iff int64) ----
    const int* l32 = (const int*)lengths_raw;
    const bool is64 = (l32[1] == 0);
    int len;
    if (is64) len = (int)(((const long long*)lengths_raw)[b]);
    else      len = l32[b];

    // ---- E column for this thread's label j, in registers ----
    float Ecol[LBL];
    #pragma unroll
    for (int i = 0; i < LBL; ++i)
        Ecol[i] = __expf(__ldg(&Tm[i * LBL + j]));

    const float* tsb = ts + (size_t)b * SEQ * LBL;

    // ---- alpha0 ----
    float a = tsb[j] + Tm[START_ID * LBL + j];

    // exact block max of alpha0 -> initial shift
    float m0 = a;
    #pragma unroll
    for (int o = 16; o > 0; o >>= 1)
        m0 = fmaxf(m0, __shfl_xor_sync(0xffffffffu, m0, o));
    if (lane == 0) wred[0][w] = m0;
    __syncthreads();
    float m_used = fmaxf(wred[0][0], wred[0][1]);
    __syncthreads();   // wred[0] is rewritten at t=1

    int buf = 0;
    float e_next = (len > 1) ? tsb[LBL + j] : 0.0f;

    // ---- forward recurrence (one barrier per step, one-step-stale max) ----
    for (int t = 1; t < len; ++t) {
        float e = e_next;
        if (t + 1 < len) e_next = tsb[(size_t)(t + 1) * LBL + j];

        // reduce current alpha's max (used NEXT step; runs in FFMA shadow)
        float wm = a;
        #pragma unroll
        for (int o = 16; o > 0; o >>= 1)
            wm = fmaxf(wm, __shfl_xor_sync(0xffffffffu, wm, o));
        if (lane == 0) wred[buf][w] = wm;

        // p uses stale (<=1 step old) max: drift bounded, exp stays safe,
        // and m_used + log(s) is exact regardless of the shift value.
        float p = __expf(a - m_used);
        sp[buf][j] = p;
        __syncthreads();

        float m_next = fmaxf(wred[buf][0], wred[buf][1]);

        // s_j = sum_i p[i] * E[i][j]; broadcast float4 LDS, E in regs,
        // 4 accumulators break the FFMA dependence chain.
        const float4* sp4 = (const float4*)sp[buf];
        float s0 = 0.f, s1 = 0.f, s2 = 0.f, s3 = 0.f;
        #pragma unroll
        for (int q = 0; q < 16; ++q) {
            float4 v = sp4[q];
            s0 = fmaf(v.x, Ecol[4*q+0], s0);
            s1 = fmaf(v.y, Ecol[4*q+1], s1);
            s2 = fmaf(v.z, Ecol[4*q+2], s2);
            s3 = fmaf(v.w, Ecol[4*q+3], s3);
        }
        float s = (s0 + s1) + (s2 + s3);

        a = m_used + __logf(s) + e;
        m_used = m_next;
        buf ^= 1;
    }

    // ---- final logsumexp(alpha + T[:, PAD]) ----
    float fa = a + Tm[j * LBL + PAD_ID];
    float fm = fa;
    #pragma unroll
    for (int o = 16; o > 0; o >>= 1)
        fm = fmaxf(fm, __shfl_xor_sync(0xffffffffu, fm, o));
    if (lane == 0) wred[buf][w] = fm;
    __syncthreads();
    fm = fmaxf(wred[buf][0], wred[buf][1]);

    float pv = __expf(fa - fm);
    #pragma unroll
    for (int o = 16; o > 0; o >>= 1)
        pv += __shfl_xor_sync(0xffffffffu, pv, o);
    if (lane == 0) sred[w] = pv;
    __syncthreads();
    float fscore = fm + __logf(sred[0] + sred[1]);

    // ---- gold path score (strided over t across the 64 threads) ----
    float g = 0.0f;
    int last_label = 0;
    if (is64) {
        const long long* lab = (const long long*)labels_raw + (size_t)b * SEQ;
        for (int t = j; t < len; t += LBL) {
            int lt = (int)lab[t];
            int pt = (t == 0) ? START_ID : (int)lab[t - 1];
            g += Tm[pt * LBL + lt] + tsb[(size_t)t * LBL + lt];
        }
        if (j == 0) last_label = (int)lab[len - 1];
    } else {
        const int* lab = (const int*)labels_raw + (size_t)b * SEQ;
        for (int t = j; t < len; t += LBL) {
            int lt = lab[t];
            int pt = (t == 0) ? START_ID : lab[t - 1];
            g += Tm[pt * LBL + lt] + tsb[(size_t)t * LBL + lt];
        }
        if (j == 0) last_label = lab[len - 1];
    }
    #pragma unroll
    for (int o = 16; o > 0; o >>= 1)
        g += __shfl_xor_sync(0xffffffffu, g, o);

    __syncthreads();            // sred reused below
    if (lane == 0) sred[w] = g;
    __syncthreads();

    if (j == 0) {
        float gold = sred[0] + sred[1] + Tm[last_label * LBL + PAD_ID];
        atomicAdd(out, (fscore - gold) * (1.0f / (float)BATCH));
    }
}

extern "C" void kernel_launch(void* const* d_in, const int* in_sizes, int n_in,
                              void* d_out, int out_size)
{
    const float* ts      = (const float*)d_in[0];
    const float* Tm      = (const float*)d_in[1];
    const void*  labels  = d_in[2];
    const void*  lengths = d_in[3];
    float* out = (float*)d_out;

    cudaMemsetAsync(out, 0, sizeof(float));
    crf_loss_kernel<<<BATCH, LBL>>>(ts, Tm, labels, lengths, out);
}

// round 2
// speedup vs baseline: 1.4273x; 1.4273x over previous
#include <cuda_runtime.h>
#include <cuda_bf16.h>

#define START_ID 62
#define PAD_ID   63
#define BATCH    512
#define SEQ      512
#define LBL      64

__device__ __forceinline__ float ex2f_(float x) {
    float y; asm("ex2.approx.f32 %0, %1;" : "=f"(y) : "f"(x)); return y;
}
__device__ __forceinline__ float lg2f_(float x) {
    float y; asm("lg2.approx.f32 %0, %1;" : "=f"(y) : "f"(x)); return y;
}

__global__ __launch_bounds__(64) void crf_loss_kernel(
    const float* __restrict__ ts,          // [B, S, L]
    const float* __restrict__ Tm,          // [L, L]
    const void*  __restrict__ labels_raw,  // [B, S] int32 or int64
    const void*  __restrict__ lengths_raw, // [B]    int32 or int64
    float* __restrict__ out)
{
    const int b    = blockIdx.x;
    const int j    = threadIdx.x;   // label 0..63
    const int lane = j & 31;
    const int w    = j >> 5;

    __shared__ __align__(16) float sp[2][LBL]; // exp2(A - M), double-buffered
    __shared__ float snext[2];                 // thread 0's A (next shift)
    __shared__ float wr[2];                    // 2-way reduce scratch
    __shared__ float sred[2];

    const float INV_LN2 = 1.44269504088896340736f;
    const float LN2     = 0.69314718055994530942f;

    // dtype detect: lengths as int32 — word[1]==0 iff data is int64
    const int* l32 = (const int*)lengths_raw;
    const bool is64 = (l32[1] == 0);
    int len;
    if (is64) len = (int)(((const long long*)lengths_raw)[b]);
    else      len = l32[b];

    // E column for this thread's label j (registers)
    float Ecol[LBL];
    #pragma unroll
    for (int i = 0; i < LBL; ++i)
        Ecol[i] = __expf(__ldg(&Tm[i * LBL + j]));

    const float* tsb = ts + (size_t)b * SEQ * LBL;

    // alpha0 in log2 domain
    float A = (tsb[j] + Tm[START_ID * LBL + j]) * INV_LN2;
    if (j == 0) snext[0] = A;

    // 4-deep emission prefetch ring (pre-scaled to log2 units)
    float er[4];
    #pragma unroll
    for (int k = 0; k < 4; ++k)
        er[k] = (1 + k < len) ? tsb[(size_t)(1 + k) * LBL + j] * INV_LN2 : 0.0f;

    __syncthreads();
    float M = snext[0];     // shift (stale by <=1 step; identity is exact for any M)
    int buf = 0;

    // ---- forward recurrence: 1 barrier/step, no reductions on the chain ----
    #pragma unroll 4
    for (int t = 1; t < len; ++t) {
        float e = er[(t - 1) & 3];
        if (t + 4 < len)
            er[(t - 1) & 3] = tsb[(size_t)(t + 4) * LBL + j] * INV_LN2;

        float P = ex2f_(A - M);
        sp[buf][j] = P;
        if (j == 0) snext[buf] = A;   // next step's shift
        __syncthreads();

        float Mn = snext[buf];

        // s_j = sum_i p_i * E[i][j]; broadcast float4 LDS, E in regs,
        // 8 accumulators to shorten the FFMA dependence chain.
        const float4* p4 = (const float4*)sp[buf];
        float s0=0.f,s1=0.f,s2=0.f,s3=0.f,s4=0.f,s5=0.f,s6=0.f,s7=0.f;
        #pragma unroll
        for (int q = 0; q < 8; ++q) {
            float4 va = p4[2*q], vb = p4[2*q+1];
            s0 = fmaf(va.x, Ecol[8*q+0], s0);
            s1 = fmaf(va.y, Ecol[8*q+1], s1);
            s2 = fmaf(va.z, Ecol[8*q+2], s2);
            s3 = fmaf(va.w, Ecol[8*q+3], s3);
            s4 = fmaf(vb.x, Ecol[8*q+4], s4);
            s5 = fmaf(vb.y, Ecol[8*q+5], s5);
            s6 = fmaf(vb.z, Ecol[8*q+6], s6);
            s7 = fmaf(vb.w, Ecol[8*q+7], s7);
        }
        float s = ((s0+s1)+(s2+s3)) + ((s4+s5)+(s6+s7));

        A = M + lg2f_(s) + e;
        M = Mn;
        buf ^= 1;
    }

    // ---- final logsumexp(alpha + T[:, PAD]) — exact, one-time ----
    float fa = A * LN2 + Tm[j * LBL + PAD_ID];
    float fm = fa;
    #pragma unroll
    for (int o = 16; o > 0; o >>= 1)
        fm = fmaxf(fm, __shfl_xor_sync(0xffffffffu, fm, o));
    __syncthreads();            // loop's shared traffic done
    if (lane == 0) wr[w] = fm;
    __syncthreads();
    fm = fmaxf(wr[0], wr[1]);

    float pv = __expf(fa - fm);
    #pragma unroll
    for (int o = 16; o > 0; o >>= 1)
        pv += __shfl_xor_sync(0xffffffffu, pv, o);
    if (lane == 0) sred[w] = pv;
    __syncthreads();
    float fscore = fm + __logf(sred[0] + sred[1]);

    // ---- gold path score (t strided across 64 threads) ----
    float g = 0.0f;
    int last_label = 0;
    if (is64) {
        const long long* lab = (const long long*)labels_raw + (size_t)b * SEQ;
        for (int t = j; t < len; t += LBL) {
            int lt = (int)lab[t];
            int pt = (t == 0) ? START_ID : (int)lab[t - 1];
            g += Tm[pt * LBL + lt] + tsb[(size_t)t * LBL + lt];
        }
        if (j == 0) last_label = (int)lab[len - 1];
    } else {
        const int* lab = (const int*)labels_raw + (size_t)b * SEQ;
        for (int t = j; t < len; t += LBL) {
            int lt = lab[t];
            int pt = (t == 0) ? START_ID : lab[t - 1];
            g += Tm[pt * LBL + lt] + tsb[(size_t)t * LBL + lt];
        }
        if (j == 0) last_label = lab[len - 1];
    }
    #pragma unroll
    for (int o = 16; o > 0; o >>= 1)
        g += __shfl_xor_sync(0xffffffffu, g, o);

    __syncthreads();
    if (lane == 0) sred[w] = g;
    __syncthreads();

    if (j == 0) {
        float gold = sred[0] + sred[1] + Tm[last_label * LBL + PAD_ID];
        atomicAdd(out, (fscore - gold) * (1.0f / (float)BATCH));
    }
}

extern "C" void kernel_launch(void* const* d_in, const int* in_sizes, int n_in,
                              void* d_out, int out_size)
{
    const float* ts      = (const float*)d_in[0];
    const float* Tm      = (const float*)d_in[1];
    const void*  labels  = d_in[2];
    const void*  lengths = d_in[3];
    float* out = (float*)d_out;

    cudaMemsetAsync(out, 0, sizeof(float));
    crf_loss_kernel<<<BATCH, LBL>>>(ts, Tm, labels, lengths, out);
}